// round 1
// baseline (speedup 1.0000x reference)
#include <cuda_runtime.h>
#include <cuda_bf16.h>
#include <cstdint>

#define NN 50000
#define EE 800000
#define ETOT (NN + EE)

// ---------------- scratch (static device globals; no allocation) ----------------
__device__ float4 g_h[NN * 32];     // GEMM output [N,128]
__device__ float4 g_agg[NN * 32];   // aggregated  [N,128]
__device__ int    g_cnt[NN];
__device__ float  g_dinv[NN];
__device__ int    g_rowptr[NN + 1];
__device__ int    g_fill[NN];
__device__ int    g_srcA[ETOT];
__device__ float  g_nrmA[ETOT];
__device__ float  g_sum[128], g_sq[128], g_scale[128], g_shift[128];
__device__ int    g_is64;

// ---------------- setup kernels ----------------
__global__ void k_detect(const int* __restrict__ ei) {
    // int64 edge_index (values < 2^31) has zero high words at odd 32-bit indices.
    __shared__ int nz;
    if (threadIdx.x == 0) nz = 0;
    __syncthreads();
    int v = ei[threadIdx.x * 2 + 1];
    if (v != 0) atomicOr(&nz, 1);
    __syncthreads();
    if (threadIdx.x == 0) g_is64 = (nz == 0) ? 1 : 0;
}

__global__ void k_init(int n) {
    int i = blockIdx.x * blockDim.x + threadIdx.x;
    if (i < n) g_cnt[i] = 1;                    // self-loop
    if (i < 128) { g_sum[i] = 0.f; g_sq[i] = 0.f; }
}

__global__ void k_count(const int* __restrict__ ei, int E) {
    int is64 = g_is64;
    for (int e = blockIdx.x * blockDim.x + threadIdx.x; e < E;
         e += gridDim.x * blockDim.x) {
        int d = is64 ? ei[2 * (E + e)] : ei[E + e];
        atomicAdd(&g_cnt[d], 1);
    }
}

__global__ void k_scan(int n) {
    __shared__ int wsum[32];
    int tid = threadIdx.x, lane = tid & 31, wid = tid >> 5;
    int carry = 0;
    for (int base = 0; base < n; base += 1024) {
        int i = base + tid;
        int v = (i < n) ? g_cnt[i] : 0;
        int x = v;
#pragma unroll
        for (int o = 1; o < 32; o <<= 1) {
            int y = __shfl_up_sync(0xffffffffu, x, o);
            if (lane >= o) x += y;
        }
        if (lane == 31) wsum[wid] = x;
        __syncthreads();
        if (wid == 0) {
            int w = wsum[lane];
#pragma unroll
            for (int o = 1; o < 32; o <<= 1) {
                int y = __shfl_up_sync(0xffffffffu, w, o);
                if (lane >= o) w += y;
            }
            wsum[lane] = w;
        }
        __syncthreads();
        int incl = x + (wid ? wsum[wid - 1] : 0);
        int total = wsum[31];
        if (i < n) {
            int excl = carry + incl - v;
            g_rowptr[i] = excl;
            g_fill[i] = excl;
            g_dinv[i] = rsqrtf((float)v);
        }
        carry += total;
        __syncthreads();
    }
    if (tid == 0) g_rowptr[n] = carry;
}

__global__ void k_fill(const int* __restrict__ ei, int E, int n) {
    int is64 = g_is64;
    int tot = E + n;
    for (int e = blockIdx.x * blockDim.x + threadIdx.x; e < tot;
         e += gridDim.x * blockDim.x) {
        int s, d;
        if (e < E) {
            if (is64) { s = ei[2 * e]; d = ei[2 * (E + e)]; }
            else      { s = ei[e];     d = ei[E + e]; }
        } else {
            s = d = e - E;              // self-loop
        }
        int pos = atomicAdd(&g_fill[d], 1);
        g_srcA[pos] = s;
        g_nrmA[pos] = g_dinv[s] * g_dinv[d];
    }
}

// ---------------- GEMM: C[M,128] = act(A[M,128]) @ B[128,128] ----------------
// TRANSFORM: A' = relu(A*scale + shift) per input channel (fused BN+ReLU of prev layer).
// Aext==nullptr -> read from g_agg. B1!=nullptr -> B = [B0 | B1], each 128x64.
template <bool TRANSFORM>
__global__ void __launch_bounds__(256) k_gemm(const float* __restrict__ Aext,
                                              const float* __restrict__ B0,
                                              const float* __restrict__ B1,
                                              int M) {
    __shared__ float Ws[16][128];
    __shared__ float As[16][68];
    __shared__ float ssc[128], ssh[128];
    const float* A = Aext ? Aext : (const float*)g_agg;

    int t = threadIdx.x, tx = t & 15, ty = t >> 4;
    int row0 = blockIdx.x * 64;

    if (TRANSFORM && t < 128) { ssc[t] = g_scale[t]; ssh[t] = g_shift[t]; }

    float acc[4][8];
#pragma unroll
    for (int r = 0; r < 4; r++)
#pragma unroll
        for (int c = 0; c < 8; c++) acc[r][c] = 0.f;

    int arow = t >> 2;            // 0..63
    int akk = (t & 3) * 4;        // 0,4,8,12
    bool arow_ok = (row0 + arow) < M;
    const float* aptr = A + (size_t)(row0 + arow) * 128 + akk;

    for (int kc = 0; kc < 128; kc += 16) {
        __syncthreads();
        // W tile (16 x 128)
#pragma unroll
        for (int i = 0; i < 8; i++) {
            int idx = t + i * 256;
            int kk = idx >> 7, c = idx & 127;
            float w;
            if (B1) w = (c < 64) ? B0[(kc + kk) * 64 + c] : B1[(kc + kk) * 64 + c - 64];
            else    w = B0[(kc + kk) * 128 + c];
            Ws[kk][c] = w;
        }
        // A tile (64 rows x 16 k), transposed into As[k][row]
        float4 av = make_float4(0.f, 0.f, 0.f, 0.f);
        if (arow_ok) av = *(const float4*)(aptr + kc);
        if (TRANSFORM) {
            av.x = fmaxf(fmaf(av.x, ssc[kc + akk + 0], ssh[kc + akk + 0]), 0.f);
            av.y = fmaxf(fmaf(av.y, ssc[kc + akk + 1], ssh[kc + akk + 1]), 0.f);
            av.z = fmaxf(fmaf(av.z, ssc[kc + akk + 2], ssh[kc + akk + 2]), 0.f);
            av.w = fmaxf(fmaf(av.w, ssc[kc + akk + 3], ssh[kc + akk + 3]), 0.f);
        }
        As[akk + 0][arow] = av.x;
        As[akk + 1][arow] = av.y;
        As[akk + 2][arow] = av.z;
        As[akk + 3][arow] = av.w;
        __syncthreads();

#pragma unroll
        for (int kk = 0; kk < 16; kk++) {
            float4 a = *(const float4*)&As[kk][ty * 4];
            float4 b0 = *(const float4*)&Ws[kk][tx * 8];
            float4 b1 = *(const float4*)&Ws[kk][tx * 8 + 4];
            float ar[4] = {a.x, a.y, a.z, a.w};
            float br[8] = {b0.x, b0.y, b0.z, b0.w, b1.x, b1.y, b1.z, b1.w};
#pragma unroll
            for (int r = 0; r < 4; r++)
#pragma unroll
                for (int c = 0; c < 8; c++) acc[r][c] = fmaf(ar[r], br[c], acc[r][c]);
        }
    }

    float* C = (float*)g_h;
#pragma unroll
    for (int r = 0; r < 4; r++) {
        int row = row0 + ty * 4 + r;
        if (row < M) {
            float4 o0 = make_float4(acc[r][0], acc[r][1], acc[r][2], acc[r][3]);
            float4 o1 = make_float4(acc[r][4], acc[r][5], acc[r][6], acc[r][7]);
            *(float4*)&C[(size_t)row * 128 + tx * 8] = o0;
            *(float4*)&C[(size_t)row * 128 + tx * 8 + 4] = o1;
        }
    }
}

// ---------------- CSR aggregation: agg[i] = sum_e nrm * h[src] ----------------
// One warp per node (grid-stride). BN: accumulate per-channel sum/sumsq in regs,
// one atomicAdd set per warp at the end. FINAL: add bias, split mu/logstd into d_out.
template <bool BN, bool FINAL>
__global__ void __launch_bounds__(256) k_agg(float* __restrict__ dout,
                                             const float* __restrict__ bmu,
                                             const float* __restrict__ bls,
                                             int n) {
    const float4* __restrict__ h = g_h;
    int lane = threadIdx.x & 31;
    int gw = (blockIdx.x * blockDim.x + threadIdx.x) >> 5;
    int nw = (gridDim.x * blockDim.x) >> 5;

    float4 bsum = make_float4(0.f, 0.f, 0.f, 0.f);
    float4 bsq = make_float4(0.f, 0.f, 0.f, 0.f);

    for (int i = gw; i < n; i += nw) {
        int beg = g_rowptr[i], end = g_rowptr[i + 1];
        float4 acc = make_float4(0.f, 0.f, 0.f, 0.f);
        for (int e = beg; e < end; e++) {
            int s = g_srcA[e];
            float nm = g_nrmA[e];
            float4 hv = h[(size_t)s * 32 + lane];
            acc.x = fmaf(nm, hv.x, acc.x);
            acc.y = fmaf(nm, hv.y, acc.y);
            acc.z = fmaf(nm, hv.z, acc.z);
            acc.w = fmaf(nm, hv.w, acc.w);
        }
        if (FINAL) {
            int ch = lane * 4;
            if (ch < 64) {
                float4 b = *(const float4*)&bmu[ch];
                float4 o = make_float4(acc.x + b.x, acc.y + b.y, acc.z + b.z, acc.w + b.w);
                *(float4*)&dout[(size_t)i * 64 + ch] = o;
            } else {
                float4 b = *(const float4*)&bls[ch - 64];
                float4 o = make_float4(acc.x + b.x, acc.y + b.y, acc.z + b.z, acc.w + b.w);
                *(float4*)&dout[(size_t)n * 64 + (size_t)i * 64 + (ch - 64)] = o;
            }
        } else {
            g_agg[(size_t)i * 32 + lane] = acc;
            if (BN) {
                bsum.x += acc.x; bsum.y += acc.y; bsum.z += acc.z; bsum.w += acc.w;
                bsq.x = fmaf(acc.x, acc.x, bsq.x);
                bsq.y = fmaf(acc.y, acc.y, bsq.y);
                bsq.z = fmaf(acc.z, acc.z, bsq.z);
                bsq.w = fmaf(acc.w, acc.w, bsq.w);
            }
        }
    }
    if (BN && !FINAL) {
        int ch = lane * 4;
        atomicAdd(&g_sum[ch + 0], bsum.x);
        atomicAdd(&g_sum[ch + 1], bsum.y);
        atomicAdd(&g_sum[ch + 2], bsum.z);
        atomicAdd(&g_sum[ch + 3], bsum.w);
        atomicAdd(&g_sq[ch + 0], bsq.x);
        atomicAdd(&g_sq[ch + 1], bsq.y);
        atomicAdd(&g_sq[ch + 2], bsq.z);
        atomicAdd(&g_sq[ch + 3], bsq.w);
    }
}

__global__ void k_bn(const float* __restrict__ gamma,
                     const float* __restrict__ beta, float invN) {
    int c = threadIdx.x;  // 128
    float mean = g_sum[c] * invN;
    float var = g_sq[c] * invN - mean * mean;
    float rs = rsqrtf(var + 1e-5f);
    float sc = gamma[c] * rs;
    g_scale[c] = sc;
    g_shift[c] = beta[c] - mean * sc;
    g_sum[c] = 0.f;
    g_sq[c] = 0.f;
}

// ---------------- launcher ----------------
extern "C" void kernel_launch(void* const* d_in, const int* in_sizes, int n_in,
                              void* d_out, int out_size) {
    const float* x   = (const float*)d_in[0];
    const int*   ei  = (const int*)d_in[1];
    const float* W1  = (const float*)d_in[2];
    const float* ga1 = (const float*)d_in[4];
    const float* be1 = (const float*)d_in[5];
    const float* W2  = (const float*)d_in[6];
    const float* ga2 = (const float*)d_in[8];
    const float* be2 = (const float*)d_in[9];
    const float* Wmu = (const float*)d_in[10];
    const float* bmu = (const float*)d_in[11];
    const float* Wls = (const float*)d_in[12];
    const float* bls = (const float*)d_in[13];

    int n = in_sizes[0] / 128;   // 50000
    int E = in_sizes[1] / 2;     // 800000
    float* outp = (float*)d_out;

    // CSR build (once per launch; reused by all 3 aggregations)
    k_detect<<<1, 256>>>(ei);
    k_init<<<(n + 255) / 256, 256>>>(n);
    k_count<<<2048, 256>>>(ei, E);
    k_scan<<<1, 1024>>>(n);
    k_fill<<<2048, 256>>>(ei, E, n);

    int gblocks = (n + 63) / 64;

    // Layer 1: h = x@W1 ; agg ; BN stats -> scale/shift  (bias cancels in BN)
    k_gemm<false><<<gblocks, 256>>>(x, W1, nullptr, n);
    k_agg<true, false><<<1184, 256>>>(nullptr, nullptr, nullptr, n);
    k_bn<<<1, 128>>>(ga1, be1, 1.0f / n);

    // Layer 2: BN+ReLU fused into GEMM A-load
    k_gemm<true><<<gblocks, 256>>>(nullptr, W2, nullptr, n);
    k_agg<true, false><<<1184, 256>>>(nullptr, nullptr, nullptr, n);
    k_bn<<<1, 128>>>(ga2, be2, 1.0f / n);

    // Heads: concat [Wmu|Wls] into one 128-wide GEMM; final agg adds bias, writes out
    k_gemm<true><<<gblocks, 256>>>(nullptr, Wmu, Wls, n);
    k_agg<false, true><<<1184, 256>>>(outp, bmu, bls, n);
}

// round 3
// speedup vs baseline: 1.2359x; 1.2359x over previous
#include <cuda_runtime.h>
#include <cuda_bf16.h>
#include <cstdint>

#define NN 50000
#define EE 800000
#define ETOT (NN + EE)

// ---------------- scratch (static device globals; no allocation) ----------------
__device__ float4 g_h[NN * 32];     // GEMM output [N,128]
__device__ float4 g_agg[NN * 32];   // aggregated  [N,128]
__device__ __align__(16) int g_cnt[NN];
__device__ float  g_dinv[NN];
__device__ int    g_rowptr[NN + 1];
__device__ int    g_fill[NN];
__device__ int2   g_edge[ETOT];     // {src, float_as_int(norm)}
__device__ float  g_sum[128], g_sq[128], g_scale[128], g_shift[128];
__device__ int    g_is64;
__device__ int    g_bsum[32], g_boff[32];
// Weight fragments, mma.m16n8k16 per-lane layout: [set][kstep(8)][ntile(16)][lane(32)]
// uint4 = {b0hi, b1hi, b0lo, b1lo}
__device__ uint4  g_Bf[3][4096];

// ---------------- setup kernels ----------------
__global__ void k_detect(const int* __restrict__ ei) {
    __shared__ int nz;
    if (threadIdx.x == 0) nz = 0;
    __syncthreads();
    if (ei[threadIdx.x * 2 + 1] != 0) atomicOr(&nz, 1);
    __syncthreads();
    if (threadIdx.x == 0) g_is64 = (nz == 0) ? 1 : 0;
}

__global__ void k_init(int n) {
    int i = blockIdx.x * blockDim.x + threadIdx.x;
    if (i < n) g_cnt[i] = 1;                    // self-loop
    if (i < 128) { g_sum[i] = 0.f; g_sq[i] = 0.f; }
}

__global__ void k_count(const int* __restrict__ ei, int E) {
    int is64 = g_is64;
    for (int e = blockIdx.x * blockDim.x + threadIdx.x; e < E;
         e += gridDim.x * blockDim.x) {
        int d = is64 ? ei[2 * (E + e)] : ei[E + e];
        atomicAdd(&g_cnt[d], 1);
    }
}

// 3-phase scan
__global__ void k_scanA(int n) {          // <<<nb, 1024>>>, 4096 elems/block
    __shared__ int wsum[32];
    int t = threadIdx.x, lane = t & 31, w = t >> 5;
    int i0 = blockIdx.x * 4096 + t * 4;
    int4 v = make_int4(0, 0, 0, 0);
    if (i0 + 3 < n) v = *(const int4*)&g_cnt[i0];
    else {
        if (i0 < n)     v.x = g_cnt[i0];
        if (i0 + 1 < n) v.y = g_cnt[i0 + 1];
        if (i0 + 2 < n) v.z = g_cnt[i0 + 2];
        if (i0 + 3 < n) v.w = g_cnt[i0 + 3];
    }
    int s0 = v.x, s1 = s0 + v.y, s2 = s1 + v.z, s3 = s2 + v.w;
    int x = s3;
#pragma unroll
    for (int o = 1; o < 32; o <<= 1) {
        int y = __shfl_up_sync(0xffffffffu, x, o);
        if (lane >= o) x += y;
    }
    if (lane == 31) wsum[w] = x;
    __syncthreads();
    if (w == 0) {
        int q = wsum[lane];
#pragma unroll
        for (int o = 1; o < 32; o <<= 1) {
            int y = __shfl_up_sync(0xffffffffu, q, o);
            if (lane >= o) q += y;
        }
        wsum[lane] = q;
    }
    __syncthreads();
    int pre = x - s3 + (w ? wsum[w - 1] : 0);
    if (i0 < n)     { g_rowptr[i0]     = pre;      g_dinv[i0]     = rsqrtf((float)v.x); }
    if (i0 + 1 < n) { g_rowptr[i0 + 1] = pre + s0; g_dinv[i0 + 1] = rsqrtf((float)v.y); }
    if (i0 + 2 < n) { g_rowptr[i0 + 2] = pre + s1; g_dinv[i0 + 2] = rsqrtf((float)v.z); }
    if (i0 + 3 < n) { g_rowptr[i0 + 3] = pre + s2; g_dinv[i0 + 3] = rsqrtf((float)v.w); }
    if (t == 0) g_bsum[blockIdx.x] = wsum[31];
}

__global__ void k_scanB(int nb, int total, int n) {   // <<<1, 32>>>
    int t = threadIdx.x;
    int v = (t < nb) ? g_bsum[t] : 0;
    int x = v;
#pragma unroll
    for (int o = 1; o < 32; o <<= 1) {
        int y = __shfl_up_sync(0xffffffffu, x, o);
        if (t >= o) x += y;
    }
    g_boff[t] = x - v;
    if (t == 0) g_rowptr[n] = total;
}

__global__ void k_scanC(int n) {
    int i = blockIdx.x * blockDim.x + threadIdx.x;
    if (i < n) {
        int rp = g_rowptr[i] + g_boff[i >> 12];
        g_rowptr[i] = rp;
        g_fill[i] = rp;
    }
}

__global__ void k_fill(const int* __restrict__ ei, int E, int n) {
    int is64 = g_is64;
    int tot = E + n;
    for (int e = blockIdx.x * blockDim.x + threadIdx.x; e < tot;
         e += gridDim.x * blockDim.x) {
        int s, d;
        if (e < E) {
            if (is64) { s = ei[2 * e]; d = ei[2 * (E + e)]; }
            else      { s = ei[e];     d = ei[E + e]; }
        } else {
            s = d = e - E;              // self-loop
        }
        int pos = atomicAdd(&g_fill[d], 1);
        g_edge[pos] = make_int2(s, __float_as_int(g_dinv[s] * g_dinv[d]));
    }
}

// ---------------- bf16 hi/lo helpers ----------------
__device__ __forceinline__ void pack_hilo(float x, float y, uint32_t& h, uint32_t& l) {
    __nv_bfloat162 hb = __floats2bfloat162_rn(x, y);
    float hx = __bfloat162float(hb.x), hy = __bfloat162float(hb.y);
    __nv_bfloat162 lb = __floats2bfloat162_rn(x - hx, y - hy);
    h = *(uint32_t*)&hb;
    l = *(uint32_t*)&lb;
}

// Pre-pack weights into exact mma fragment layout (once per launch).
// B fragment (col-major n8k16): b0 holds k=(lane%4)*2+{0,1}, n=lane>>2; b1 holds k+8.
__global__ void k_prepB(const float* __restrict__ W1, const float* __restrict__ W2,
                        const float* __restrict__ Wmu, const float* __restrict__ Wls) {
    int idx = blockIdx.x * blockDim.x + threadIdx.x;   // 3*8*16*32 = 12288
    if (idx >= 12288) return;
    int lane  = idx & 31;
    int ntile = (idx >> 5) & 15;
    int kstep = (idx >> 9) & 7;
    int set   = idx >> 12;
    int n  = ntile * 8 + (lane >> 2);
    int k0 = kstep * 16 + (lane & 3) * 2;

    float w[4];
#pragma unroll
    for (int j = 0; j < 4; j++) {
        int k = k0 + (j & 1) + (j >> 1) * 8;   // k0, k0+1, k0+8, k0+9
        float v;
        if (set == 0)      v = W1[k * 128 + n];
        else if (set == 1) v = W2[k * 128 + n];
        else               v = (n < 64) ? Wmu[k * 64 + n] : Wls[k * 64 + (n - 64)];
        w[j] = v;
    }
    uint4 f;
    pack_hilo(w[0], w[1], f.x, f.z);
    pack_hilo(w[2], w[3], f.y, f.w);
    g_Bf[set][kstep * 512 + ntile * 32 + lane] = f;
}

// ---------------- HMMA GEMM: h[M,128] = act(A[M,128]) @ W[128,128] ----------------
// bf16 hi/lo split, 3 mma passes, fp32 accum. TR: fused BN(scale,shift)+ReLU on A.
__device__ __forceinline__ void mma16816(float c[4], const uint32_t a[4],
                                         uint32_t b0, uint32_t b1) {
    asm volatile(
        "mma.sync.aligned.m16n8k16.row.col.f32.bf16.bf16.f32 "
        "{%0,%1,%2,%3}, {%4,%5,%6,%7}, {%8,%9}, {%0,%1,%2,%3};"
        : "+f"(c[0]), "+f"(c[1]), "+f"(c[2]), "+f"(c[3])
        : "r"(a[0]), "r"(a[1]), "r"(a[2]), "r"(a[3]), "r"(b0), "r"(b1));
}

#define GEMM_SMEM (65536 + 1024)
template <bool TR>
__global__ void __launch_bounds__(256) k_mgemm(const float* __restrict__ Aext,
                                               int set, int M) {
    extern __shared__ char sraw[];
    uint4* Bs = (uint4*)sraw;                       // 4096 x 16B = 64KB
    float* ssc = (float*)(sraw + 65536);
    float* ssh = ssc + 128;

    const float* A = Aext ? Aext : (const float*)g_agg;
    int t = threadIdx.x, lane = t & 31, w = t >> 5;

    const uint4* src = &g_Bf[set][0];
#pragma unroll
    for (int i = 0; i < 16; i++) Bs[t + i * 256] = src[t + i * 256];
    if (TR && t < 128) { ssc[t] = g_scale[t]; ssh[t] = g_shift[t]; }
    __syncthreads();

    int r0 = blockIdx.x * 128 + w * 16 + (lane >> 2);
    int r1 = r0 + 8;
    bool ok0 = r0 < M, ok1 = r1 < M;
    const float* a0p = A + (size_t)(ok0 ? r0 : 0) * 128;
    const float* a1p = A + (size_t)(ok1 ? r1 : 0) * 128;
    int kq = (lane & 3) * 2;

    float c[16][4];
#pragma unroll
    for (int nt = 0; nt < 16; nt++)
#pragma unroll
        for (int j = 0; j < 4; j++) c[nt][j] = 0.f;

#pragma unroll
    for (int ks = 0; ks < 8; ks++) {
        int k0 = ks * 16 + kq;
        float2 A00 = ok0 ? *(const float2*)(a0p + k0)     : make_float2(0.f, 0.f);
        float2 A01 = ok0 ? *(const float2*)(a0p + k0 + 8) : make_float2(0.f, 0.f);
        float2 A10 = ok1 ? *(const float2*)(a1p + k0)     : make_float2(0.f, 0.f);
        float2 A11 = ok1 ? *(const float2*)(a1p + k0 + 8) : make_float2(0.f, 0.f);
        if (TR) {
            float s0 = ssc[k0], s1 = ssc[k0 + 1], s8 = ssc[k0 + 8], s9 = ssc[k0 + 9];
            float h0 = ssh[k0], h1 = ssh[k0 + 1], h8 = ssh[k0 + 8], h9 = ssh[k0 + 9];
            A00.x = fmaxf(fmaf(A00.x, s0, h0), 0.f);
            A00.y = fmaxf(fmaf(A00.y, s1, h1), 0.f);
            A10.x = fmaxf(fmaf(A10.x, s0, h0), 0.f);
            A10.y = fmaxf(fmaf(A10.y, s1, h1), 0.f);
            A01.x = fmaxf(fmaf(A01.x, s8, h8), 0.f);
            A01.y = fmaxf(fmaf(A01.y, s9, h9), 0.f);
            A11.x = fmaxf(fmaf(A11.x, s8, h8), 0.f);
            A11.y = fmaxf(fmaf(A11.y, s9, h9), 0.f);
        }
        uint32_t ah[4], al[4];
        pack_hilo(A00.x, A00.y, ah[0], al[0]);
        pack_hilo(A10.x, A10.y, ah[1], al[1]);
        pack_hilo(A01.x, A01.y, ah[2], al[2]);
        pack_hilo(A11.x, A11.y, ah[3], al[3]);

        const uint4* brow = &Bs[ks * 512 + lane];
#pragma unroll
        for (int nt = 0; nt < 16; nt++) {
            uint4 bb = brow[nt * 32];
            mma16816(c[nt], ah, bb.x, bb.y);   // hi * hi
            mma16816(c[nt], ah, bb.z, bb.w);   // hi * lo
            mma16816(c[nt], al, bb.x, bb.y);   // lo * hi
        }
    }

    float* out = (float*)g_h;
    int col0 = (lane & 3) * 2;
#pragma unroll
    for (int nt = 0; nt < 16; nt++) {
        int n0 = nt * 8 + col0;
        if (ok0) *(float2*)&out[(size_t)r0 * 128 + n0] = make_float2(c[nt][0], c[nt][1]);
        if (ok1) *(float2*)&out[(size_t)r1 * 128 + n0] = make_float2(c[nt][2], c[nt][3]);
    }
}

// ---------------- CSR aggregation: agg[i] = sum_e nrm * h[src] ----------------
template <bool BN, bool FINAL>
__global__ void __launch_bounds__(256) k_agg(float* __restrict__ dout,
                                             const float* __restrict__ bmu,
                                             const float* __restrict__ bls,
                                             int n) {
    const float4* __restrict__ h = g_h;
    const int2* __restrict__ ge = g_edge;
    int lane = threadIdx.x & 31;
    int gw = (blockIdx.x * blockDim.x + threadIdx.x) >> 5;
    int nw = (gridDim.x * blockDim.x) >> 5;

    float4 bsum = make_float4(0.f, 0.f, 0.f, 0.f);
    float4 bsq = make_float4(0.f, 0.f, 0.f, 0.f);

    for (int i = gw; i < n; i += nw) {
        int beg = g_rowptr[i], end = g_rowptr[i + 1];
        float4 acc = make_float4(0.f, 0.f, 0.f, 0.f);
        int e = beg;
        for (; e + 4 <= end; e += 4) {
            int2 p0 = ge[e], p1 = ge[e + 1], p2 = ge[e + 2], p3 = ge[e + 3];
            float4 h0 = h[(size_t)p0.x * 32 + lane];
            float4 h1 = h[(size_t)p1.x * 32 + lane];
            float4 h2 = h[(size_t)p2.x * 32 + lane];
            float4 h3 = h[(size_t)p3.x * 32 + lane];
            float n0 = __int_as_float(p0.y), n1 = __int_as_float(p1.y);
            float n2 = __int_as_float(p2.y), n3 = __int_as_float(p3.y);
            acc.x = fmaf(n0, h0.x, acc.x); acc.y = fmaf(n0, h0.y, acc.y);
            acc.z = fmaf(n0, h0.z, acc.z); acc.w = fmaf(n0, h0.w, acc.w);
            acc.x = fmaf(n1, h1.x, acc.x); acc.y = fmaf(n1, h1.y, acc.y);
            acc.z = fmaf(n1, h1.z, acc.z); acc.w = fmaf(n1, h1.w, acc.w);
            acc.x = fmaf(n2, h2.x, acc.x); acc.y = fmaf(n2, h2.y, acc.y);
            acc.z = fmaf(n2, h2.z, acc.z); acc.w = fmaf(n2, h2.w, acc.w);
            acc.x = fmaf(n3, h3.x, acc.x); acc.y = fmaf(n3, h3.y, acc.y);
            acc.z = fmaf(n3, h3.z, acc.z); acc.w = fmaf(n3, h3.w, acc.w);
        }
        for (; e < end; e++) {
            int2 p = ge[e];
            float nm = __int_as_float(p.y);
            float4 hv = h[(size_t)p.x * 32 + lane];
            acc.x = fmaf(nm, hv.x, acc.x); acc.y = fmaf(nm, hv.y, acc.y);
            acc.z = fmaf(nm, hv.z, acc.z); acc.w = fmaf(nm, hv.w, acc.w);
        }
        if (FINAL) {
            int ch = lane * 4;
            if (ch < 64) {
                float4 b = *(const float4*)&bmu[ch];
                *(float4*)&dout[(size_t)i * 64 + ch] =
                    make_float4(acc.x + b.x, acc.y + b.y, acc.z + b.z, acc.w + b.w);
            } else {
                float4 b = *(const float4*)&bls[ch - 64];
                *(float4*)&dout[(size_t)n * 64 + (size_t)i * 64 + (ch - 64)] =
                    make_float4(acc.x + b.x, acc.y + b.y, acc.z + b.z, acc.w + b.w);
            }
        } else {
            g_agg[(size_t)i * 32 + lane] = acc;
            if (BN) {
                bsum.x += acc.x; bsum.y += acc.y; bsum.z += acc.z; bsum.w += acc.w;
                bsq.x = fmaf(acc.x, acc.x, bsq.x);
                bsq.y = fmaf(acc.y, acc.y, bsq.y);
                bsq.z = fmaf(acc.z, acc.z, bsq.z);
                bsq.w = fmaf(acc.w, acc.w, bsq.w);
            }
        }
    }
    if (BN && !FINAL) {
        int ch = lane * 4;
        atomicAdd(&g_sum[ch + 0], bsum.x); atomicAdd(&g_sum[ch + 1], bsum.y);
        atomicAdd(&g_sum[ch + 2], bsum.z); atomicAdd(&g_sum[ch + 3], bsum.w);
        atomicAdd(&g_sq[ch + 0], bsq.x);   atomicAdd(&g_sq[ch + 1], bsq.y);
        atomicAdd(&g_sq[ch + 2], bsq.z);   atomicAdd(&g_sq[ch + 3], bsq.w);
    }
}

__global__ void k_bn(const float* __restrict__ gamma,
                     const float* __restrict__ beta, float invN) {
    int c = threadIdx.x;  // 128
    float mean = g_sum[c] * invN;
    float var = g_sq[c] * invN - mean * mean;
    float rs = rsqrtf(var + 1e-5f);
    float sc = gamma[c] * rs;
    g_scale[c] = sc;
    g_shift[c] = beta[c] - mean * sc;
    g_sum[c] = 0.f;
    g_sq[c] = 0.f;
}

// ---------------- launcher ----------------
extern "C" void kernel_launch(void* const* d_in, const int* in_sizes, int n_in,
                              void* d_out, int out_size) {
    const float* x   = (const float*)d_in[0];
    const int*   ei  = (const int*)d_in[1];
    const float* W1  = (const float*)d_in[2];
    const float* ga1 = (const float*)d_in[4];
    const float* be1 = (const float*)d_in[5];
    const float* W2  = (const float*)d_in[6];
    const float* ga2 = (const float*)d_in[8];
    const float* be2 = (const float*)d_in[9];
    const float* Wmu = (const float*)d_in[10];
    const float* bmu = (const float*)d_in[11];
    const float* Wls = (const float*)d_in[12];
    const float* bls = (const float*)d_in[13];

    int n = in_sizes[0] / 128;   // 50000
    int E = in_sizes[1] / 2;     // 800000
    float* outp = (float*)d_out;

    cudaFuncSetAttribute(k_mgemm<false>, cudaFuncAttributeMaxDynamicSharedMemorySize, GEMM_SMEM);
    cudaFuncSetAttribute(k_mgemm<true>,  cudaFuncAttributeMaxDynamicSharedMemorySize, GEMM_SMEM);

    // CSR build (reused by all 3 aggregations)
    k_detect<<<1, 256>>>(ei);
    k_init<<<(n + 255) / 256, 256>>>(n);
    k_count<<<1024, 256>>>(ei, E);
    int nb = (n + 4095) / 4096;
    k_scanA<<<nb, 1024>>>(n);
    k_scanB<<<1, 32>>>(nb, n + E, n);
    k_scanC<<<(n + 255) / 256, 256>>>(n);
    k_fill<<<1024, 256>>>(ei, E, n);
    k_prepB<<<48, 256>>>(W1, W2, Wmu, Wls);

    int gb = (n + 127) / 128;

    // Layer 1 (bias cancels in BN)
    k_mgemm<false><<<gb, 256, GEMM_SMEM>>>(x, 0, n);
    k_agg<true, false><<<1184, 256>>>(nullptr, nullptr, nullptr, n);
    k_bn<<<1, 128>>>(ga1, be1, 1.0f / n);

    // Layer 2 (BN+ReLU fused into GEMM A-load)
    k_mgemm<true><<<gb, 256, GEMM_SMEM>>>(nullptr, 1, n);
    k_agg<true, false><<<1184, 256>>>(nullptr, nullptr, nullptr, n);
    k_bn<<<1, 128>>>(ga2, be2, 1.0f / n);

    // Heads: [Wmu|Wls] as one 128-wide GEMM; final agg adds bias, writes out
    k_mgemm<true><<<gb, 256, GEMM_SMEM>>>(nullptr, 2, n);
    k_agg<false, true><<<1184, 256>>>(outp, bmu, bls, n);
}